// round 13
// baseline (speedup 1.0000x reference)
#include <cuda_runtime.h>

typedef unsigned long long ull;

#define NBATCH 2
#define SEQ 1024
#define DMODEL 768
#define NH 12
#define DH 64
#define NTOK (NBATCH*SEQ)
#define NN (SEQ*SEQ)
#define ATTN_SCALE 0.125f

// ---------------- scratch (device globals: allocation-free) ----------------
__device__ float g_xn[NTOK*DMODEL];
__device__ float g_q[NBATCH*NH*SEQ*DH];
__device__ float g_k[NBATCH*NH*SEQ*DH];
__device__ float g_v[NBATCH*NH*SEQ*DH];
__device__ float g_attn[NBATCH*NH*NN];   // 100.7 MB; softmax+mix in place
__device__ float g_av[NTOK*DMODEL];
__device__ float g_M[NH*NH];

// ---------------- f32x2 packed-FMA helpers (FFMA2, PTX-only path) ----------
__device__ __forceinline__ ull pk2(float x) {
    ull r; asm("mov.b64 %0, {%1, %1};" : "=l"(r) : "f"(x)); return r;
}
__device__ __forceinline__ void fma2(ull& d, ull a, ull b) {
    asm("fma.rn.f32x2 %0, %1, %2, %0;" : "+l"(d) : "l"(a), "l"(b));
}
__device__ __forceinline__ float2 up2(ull v) {
    float2 r; asm("mov.b64 {%0, %1}, %2;" : "=f"(r.x), "=f"(r.y) : "l"(v)); return r;
}

// ---------------- LayerNorm ----------------
__global__ __launch_bounds__(256) void ln_kernel(
    const float* __restrict__ x, const float* __restrict__ g, const float* __restrict__ b)
{
    const int row = blockIdx.x;
    const int t = threadIdx.x;
    const float* xr = x + (size_t)row * DMODEL;
    float v0 = xr[t], v1 = xr[t + 256], v2 = xr[t + 512];
    float s = v0 + v1 + v2;
    float q = v0*v0 + v1*v1 + v2*v2;
    __shared__ float rs[8], rq[8], mb[2];
    #pragma unroll
    for (int o = 16; o; o >>= 1) {
        s += __shfl_xor_sync(0xffffffffu, s, o);
        q += __shfl_xor_sync(0xffffffffu, q, o);
    }
    if ((t & 31) == 0) { rs[t >> 5] = s; rq[t >> 5] = q; }
    __syncthreads();
    if (t == 0) {
        float ts = 0.f, tq = 0.f;
        #pragma unroll
        for (int i = 0; i < 8; i++) { ts += rs[i]; tq += rq[i]; }
        float mean = ts * (1.0f / DMODEL);
        float var  = tq * (1.0f / DMODEL) - mean * mean;
        mb[0] = mean; mb[1] = rsqrtf(var + 1e-5f);
    }
    __syncthreads();
    const float mean = mb[0], rstd = mb[1];
    float* o = g_xn + (size_t)row * DMODEL;
    o[t]       = (v0 - mean) * rstd * g[t]       + b[t];
    o[t + 256] = (v1 - mean) * rstd * g[t + 256] + b[t + 256];
    o[t + 512] = (v2 - mean) * rstd * g[t + 512] + b[t + 512];
}

// ---------------- M = (-0.5 * theta) @ gnn_w  (12x12) ----------------
__global__ void m_kernel(const float* __restrict__ theta, const float* __restrict__ gnn)
{
    int t = threadIdx.x;
    if (t < NH * NH) {
        int i = t / NH, j = t % NH;
        float s = 0.f;
        #pragma unroll
        for (int k = 0; k < NH; k++) s += theta[i * NH + k] * gnn[k * NH + j];
        g_M[t] = -0.5f * s;
    }
}

// ================= 128x128 NT GEMM core, 8x8 per thread ====================
// C[128m x 128n] = A[128 x K] * B[128 x K]^T, A/B row-major contiguous in K.
// Duplicated-A smem: As[kk][2m],[2m+1] both hold A[m][kk] so a broadcast pair
// (a,a) is a single LDS.64. B read as f32x2 vectors. acc[i][jp] holds
// (C[mb+i][nb+2jp], C[mb+i][nb+2jp+1]).
// 256 threads; warp layout 4x2 (warps) x lanes 4x8: thread tile 8m x 8n.
template<int KDIM>
__device__ __forceinline__ void gemm_nt128(
    const float* __restrict__ A, int lda,
    const float* __restrict__ B, int ldb,
    ull (&acc)[8][4], int mb, int nb)
{
    __shared__ __align__(16) float As[16][256];   // duplicated pairs: 16 KB
    __shared__ __align__(16) float Bs[16][132];   // padded: 8.25 KB
    const int t = threadIdx.x;
    const int lrow = t >> 1;          // 0..127 (row of A/B tile)
    const int kq = (t & 1) * 8;       // 0 or 8 (k quad)
    const float* Aptr = A + (size_t)lrow * lda + kq;
    const float* Bptr = B + (size_t)lrow * ldb + kq;

    for (int k0 = 0; k0 < KDIM; k0 += 16) {
        float4 av0 = *(const float4*)(Aptr + k0);
        float4 av1 = *(const float4*)(Aptr + k0 + 4);
        float4 bv0 = *(const float4*)(Bptr + k0);
        float4 bv1 = *(const float4*)(Bptr + k0 + 4);
        __syncthreads();
        *(ull*)&As[kq + 0][2 * lrow] = pk2(av0.x);
        *(ull*)&As[kq + 1][2 * lrow] = pk2(av0.y);
        *(ull*)&As[kq + 2][2 * lrow] = pk2(av0.z);
        *(ull*)&As[kq + 3][2 * lrow] = pk2(av0.w);
        *(ull*)&As[kq + 4][2 * lrow] = pk2(av1.x);
        *(ull*)&As[kq + 5][2 * lrow] = pk2(av1.y);
        *(ull*)&As[kq + 6][2 * lrow] = pk2(av1.z);
        *(ull*)&As[kq + 7][2 * lrow] = pk2(av1.w);
        Bs[kq + 0][lrow] = bv0.x;  Bs[kq + 1][lrow] = bv0.y;
        Bs[kq + 2][lrow] = bv0.z;  Bs[kq + 3][lrow] = bv0.w;
        Bs[kq + 4][lrow] = bv1.x;  Bs[kq + 5][lrow] = bv1.y;
        Bs[kq + 6][lrow] = bv1.z;  Bs[kq + 7][lrow] = bv1.w;
        __syncthreads();
        #pragma unroll
        for (int kk = 0; kk < 16; kk++) {
            ull b0 = *(const ull*)&Bs[kk][nb + 0];
            ull b1 = *(const ull*)&Bs[kk][nb + 2];
            ull b2 = *(const ull*)&Bs[kk][nb + 4];
            ull b3 = *(const ull*)&Bs[kk][nb + 6];
            #pragma unroll
            for (int i = 0; i < 8; i++) {
                ull a = *(const ull*)&As[kk][2 * (mb + i)];
                fma2(acc[i][0], a, b0);
                fma2(acc[i][1], a, b1);
                fma2(acc[i][2], a, b2);
                fma2(acc[i][3], a, b3);
            }
        }
    }
}

__device__ __forceinline__ void thread_mn(int& mb, int& nb) {
    const int t = threadIdx.x;
    const int warp = t >> 5, lane = t & 31;
    mb = (warp & 3) * 32 + (lane >> 3) * 8;   // 0..120, step 8
    nb = (warp >> 2) * 64 + (lane & 7) * 8;   // 0..120, step 8
}

// row i of the thread tile as two float4s (cols nb..nb+7)
__device__ __forceinline__ void row_f4(const ull* a4, float4& lo, float4& hi) {
    float2 p0 = up2(a4[0]), p1 = up2(a4[1]), p2 = up2(a4[2]), p3 = up2(a4[3]);
    lo = make_float4(p0.x, p0.y, p1.x, p1.y);
    hi = make_float4(p2.x, p2.y, p3.x, p3.y);
}

// ---------------- QKV GEMM: [2048x768] @ w_qkv^T[768x2304], scatter per head --
__global__ __launch_bounds__(256) void qkv_kernel(const float* __restrict__ w)
{
    ull acc[8][4];
    #pragma unroll
    for (int i = 0; i < 8; i++)
        #pragma unroll
        for (int j = 0; j < 4; j++) acc[i][j] = 0ull;
    int mb, nb; thread_mn(mb, nb);

    const float* A = g_xn + (size_t)blockIdx.y * 128 * DMODEL;
    const float* B = w    + (size_t)blockIdx.x * 128 * DMODEL;
    gemm_nt128<DMODEL>(A, DMODEL, B, DMODEL, acc, mb, nb);

    const int c0 = blockIdx.x * 128 + nb;         // global output column
    const int sec = c0 / DMODEL;                  // 0=q,1=k,2=v (8-col span never straddles)
    const int rem = c0 - sec * DMODEL;
    const int h = rem >> 6, d = rem & 63;         // d..d+7 within one head
    float* dst = (sec == 0) ? g_q : (sec == 1) ? g_k : g_v;

    #pragma unroll
    for (int i = 0; i < 8; i++) {
        float4 lo, hi; row_f4(acc[i], lo, hi);
        int m = blockIdx.y * 128 + mb + i;
        int bt = m >> 10, tok = m & 1023;         // 128-row tile never straddles batch
        float* p = dst + ((size_t)((bt * NH + h) * SEQ + tok)) * DH + d;
        *(float4*)p = lo;
        *(float4*)(p + 4) = hi;
    }
}

// ---------------- S = Q @ K^T * scale  per (b,h) ----------------
__global__ __launch_bounds__(256) void qk_kernel()
{
    const int bh = blockIdx.z;
    ull acc[8][4];
    #pragma unroll
    for (int i = 0; i < 8; i++)
        #pragma unroll
        for (int j = 0; j < 4; j++) acc[i][j] = 0ull;
    int mb, nb; thread_mn(mb, nb);

    const float* A = g_q + (size_t)bh * SEQ * DH + (size_t)blockIdx.y * 128 * DH;
    const float* B = g_k + (size_t)bh * SEQ * DH + (size_t)blockIdx.x * 128 * DH;
    gemm_nt128<DH>(A, DH, B, DH, acc, mb, nb);

    float* out = g_attn + (size_t)bh * NN;
    const int n0 = blockIdx.x * 128 + nb;
    #pragma unroll
    for (int i = 0; i < 8; i++) {
        float4 lo, hi; row_f4(acc[i], lo, hi);
        int m = blockIdx.y * 128 + mb + i;
        float* p = &out[(size_t)m * SEQ + n0];
        *(float4*)p = make_float4(lo.x * ATTN_SCALE, lo.y * ATTN_SCALE,
                                  lo.z * ATTN_SCALE, lo.w * ATTN_SCALE);
        *(float4*)(p + 4) = make_float4(hi.x * ATTN_SCALE, hi.y * ATTN_SCALE,
                                        hi.z * ATTN_SCALE, hi.w * ATTN_SCALE);
    }
}

// ---------------- fused softmax + head-mix, IN PLACE over g_attn ------------
__global__ __launch_bounds__(256) void softmax_mix_kernel()
{
    __shared__ float Ms[NH * NH];
    __shared__ float red[8];
    __shared__ float bc;
    const int t = threadIdx.x;
    const int b = blockIdx.x >> 10;
    const int n = blockIdx.x & (SEQ - 1);
    if (t < NH * NH) Ms[t] = g_M[t];

    float4 a[NH];
    #pragma unroll
    for (int h = 0; h < NH; h++) {
        float4* p = (float4*)(g_attn + ((size_t)(b * NH + h) * SEQ + n) * SEQ);
        float4 v = p[t];
        float m = fmaxf(fmaxf(v.x, v.y), fmaxf(v.z, v.w));
        #pragma unroll
        for (int o = 16; o; o >>= 1) m = fmaxf(m, __shfl_xor_sync(0xffffffffu, m, o));
        if ((t & 31) == 0) red[t >> 5] = m;
        __syncthreads();
        if (t == 0) {
            float x = red[0];
            #pragma unroll
            for (int i = 1; i < 8; i++) x = fmaxf(x, red[i]);
            bc = x;
        }
        __syncthreads();
        m = bc;
        v.x = __expf(v.x - m); v.y = __expf(v.y - m);
        v.z = __expf(v.z - m); v.w = __expf(v.w - m);
        float s = v.x + v.y + v.z + v.w;
        #pragma unroll
        for (int o = 16; o; o >>= 1) s += __shfl_xor_sync(0xffffffffu, s, o);
        __syncthreads();                 // all threads done reading bc (max)
        if ((t & 31) == 0) red[t >> 5] = s;
        __syncthreads();
        if (t == 0) {
            float x = 0.f;
            #pragma unroll
            for (int i = 0; i < 8; i++) x += red[i];
            bc = x;
        }
        __syncthreads();
        const float inv = 1.0f / bc;
        a[h] = make_float4(v.x * inv, v.y * inv, v.z * inv, v.w * inv);
        __syncthreads();                 // all threads done reading bc (sum)
    }

    #pragma unroll
    for (int i = 0; i < NH; i++) {
        float ax = 0.f, ay = 0.f, az = 0.f, aw = 0.f;
        #pragma unroll
        for (int k = 0; k < NH; k++) {
            float mm = Ms[i * NH + k];
            ax = fmaf(mm, a[k].x, ax); ay = fmaf(mm, a[k].y, ay);
            az = fmaf(mm, a[k].z, az); aw = fmaf(mm, a[k].w, aw);
        }
        float4 r;
        r.x = a[i].x + fmaxf(ax, 0.f); r.y = a[i].y + fmaxf(ay, 0.f);
        r.z = a[i].z + fmaxf(az, 0.f); r.w = a[i].w + fmaxf(aw, 0.f);
        float4* p = (float4*)(g_attn + ((size_t)(b * NH + i) * SEQ + n) * SEQ);
        p[t] = r;
    }
}

// ---------------- out_h = P2 @ V per (b,h): C[128n x 64d], K = 1024 ----------
__global__ __launch_bounds__(256) void av_kernel()
{
    __shared__ __align__(16) float Ast[32][130];   // [m][n] transposed P2 tile
    __shared__ __align__(16) float Bs2[32][64];    // [m][d]
    const int t = threadIdx.x, lane = t & 31, warp = t >> 5;
    const int bh = blockIdx.y;
    const int n0 = blockIdx.x * 128;
    const float* Ap = g_attn + (size_t)bh * NN + (size_t)n0 * SEQ;
    const float* Bp = g_v + (size_t)bh * SEQ * DH;
    const int nb = warp * 16 + (lane >> 4) * 8;
    const int db = (lane & 15) * 4;
    ull acc[4][4];
    #pragma unroll
    for (int i = 0; i < 4; i++)
        #pragma unroll
        for (int j = 0; j < 4; j++) acc[i][j] = 0ull;

    const int arow = t >> 1;              // 0..127
    const int acolq = (t & 1) * 16;       // 0 or 16
    const int vi0 = t, vi1 = t + 256;

    for (int k0 = 0; k0 < SEQ; k0 += 32) {
        float4 a0 = *(const float4*)(Ap + (size_t)arow * SEQ + k0 + acolq + 0);
        float4 a1 = *(const float4*)(Ap + (size_t)arow * SEQ + k0 + acolq + 4);
        float4 a2 = *(const float4*)(Ap + (size_t)arow * SEQ + k0 + acolq + 8);
        float4 a3 = *(const float4*)(Ap + (size_t)arow * SEQ + k0 + acolq + 12);
        float4 v0 = *(const float4*)(Bp + (size_t)(k0 + (vi0 >> 4)) * DH + (vi0 & 15) * 4);
        float4 v1 = *(const float4*)(Bp + (size_t)(k0 + (vi1 >> 4)) * DH + (vi1 & 15) * 4);
        __syncthreads();
        Ast[acolq + 0][arow] = a0.x;  Ast[acolq + 1][arow] = a0.y;
        Ast[acolq + 2][arow] = a0.z;  Ast[acolq + 3][arow] = a0.w;
        Ast[acolq + 4][arow] = a1.x;  Ast[acolq + 5][arow] = a1.y;
        Ast[acolq + 6][arow] = a1.z;  Ast[acolq + 7][arow] = a1.w;
        Ast[acolq + 8][arow] = a2.x;  Ast[acolq + 9][arow] = a2.y;
        Ast[acolq + 10][arow] = a2.z; Ast[acolq + 11][arow] = a2.w;
        Ast[acolq + 12][arow] = a3.x; Ast[acolq + 13][arow] = a3.y;
        Ast[acolq + 14][arow] = a3.z; Ast[acolq + 15][arow] = a3.w;
        *(float4*)&Bs2[vi0 >> 4][(vi0 & 15) * 4] = v0;
        *(float4*)&Bs2[vi1 >> 4][(vi1 & 15) * 4] = v1;
        __syncthreads();
        #pragma unroll
        for (int kk = 0; kk < 32; kk++) {
            ull a0u = *(const ull*)&Ast[kk][nb + 0];
            ull a1u = *(const ull*)&Ast[kk][nb + 2];
            ull a2u = *(const ull*)&Ast[kk][nb + 4];
            ull a3u = *(const ull*)&Ast[kk][nb + 6];
            ull b0 = pk2(Bs2[kk][db + 0]);
            ull b1 = pk2(Bs2[kk][db + 1]);
            ull b2 = pk2(Bs2[kk][db + 2]);
            ull b3 = pk2(Bs2[kk][db + 3]);
            fma2(acc[0][0], a0u, b0); fma2(acc[0][1], a0u, b1);
            fma2(acc[0][2], a0u, b2); fma2(acc[0][3], a0u, b3);
            fma2(acc[1][0], a1u, b0); fma2(acc[1][1], a1u, b1);
            fma2(acc[1][2], a1u, b2); fma2(acc[1][3], a1u, b3);
            fma2(acc[2][0], a2u, b0); fma2(acc[2][1], a2u, b1);
            fma2(acc[2][2], a2u, b2); fma2(acc[2][3], a2u, b3);
            fma2(acc[3][0], a3u, b0); fma2(acc[3][1], a3u, b1);
            fma2(acc[3][2], a3u, b2); fma2(acc[3][3], a3u, b3);
        }
    }

    const int bt = bh / NH, h = bh % NH;
    #pragma unroll
    for (int i = 0; i < 4; i++) {
        float2 c0v = up2(acc[i][0]), c1v = up2(acc[i][1]);
        float2 c2v = up2(acc[i][2]), c3v = up2(acc[i][3]);
        int n = n0 + nb + 2 * i;
        float* o0 = g_av + (size_t)(bt * SEQ + n) * DMODEL + h * DH + db;
        float* o1 = g_av + (size_t)(bt * SEQ + n + 1) * DMODEL + h * DH + db;
        *(float4*)o0 = make_float4(c0v.x, c1v.x, c2v.x, c3v.x);
        *(float4*)o1 = make_float4(c0v.y, c1v.y, c2v.y, c3v.y);
    }
}

// ---------------- out = g_av @ w_out^T + b_out ----------------
__global__ __launch_bounds__(256) void proj_kernel(
    const float* __restrict__ w, const float* __restrict__ bias, float* __restrict__ out)
{
    ull acc[8][4];
    #pragma unroll
    for (int i = 0; i < 8; i++)
        #pragma unroll
        for (int j = 0; j < 4; j++) acc[i][j] = 0ull;
    int mb, nb; thread_mn(mb, nb);

    const float* A = g_av + (size_t)blockIdx.y * 128 * DMODEL;
    const float* B = w    + (size_t)blockIdx.x * 128 * DMODEL;
    gemm_nt128<DMODEL>(A, DMODEL, B, DMODEL, acc, mb, nb);

    const int c0 = blockIdx.x * 128 + nb;
    const float4 bb0 = *(const float4*)&bias[c0];
    const float4 bb1 = *(const float4*)&bias[c0 + 4];
    #pragma unroll
    for (int i = 0; i < 8; i++) {
        float4 lo, hi; row_f4(acc[i], lo, hi);
        int m = blockIdx.y * 128 + mb + i;
        float* p = &out[(size_t)m * DMODEL + c0];
        *(float4*)p = make_float4(lo.x + bb0.x, lo.y + bb0.y, lo.z + bb0.z, lo.w + bb0.w);
        *(float4*)(p + 4) = make_float4(hi.x + bb1.x, hi.y + bb1.y, hi.z + bb1.z, hi.w + bb1.w);
    }
}

// ---------------- launch ----------------
extern "C" void kernel_launch(void* const* d_in, const int* in_sizes, int n_in,
                              void* d_out, int out_size)
{
    const float* x     = (const float*)d_in[0];
    const float* ln_g  = (const float*)d_in[1];
    const float* ln_b  = (const float*)d_in[2];
    const float* w_qkv = (const float*)d_in[3];
    const float* w_out = (const float*)d_in[4];
    const float* b_out = (const float*)d_in[5];
    const float* theta = (const float*)d_in[6];
    const float* gnn_w = (const float*)d_in[7];
    float* out = (float*)d_out;

    ln_kernel<<<NTOK, 256>>>(x, ln_g, ln_b);
    m_kernel<<<1, 160>>>(theta, gnn_w);
    qkv_kernel<<<dim3(18, 16), 256>>>(w_qkv);                 // 2304/128 x 2048/128
    qk_kernel<<<dim3(8, 8, NBATCH * NH), 256>>>();            // 1024/128 x 1024/128 x 24
    softmax_mix_kernel<<<NBATCH * SEQ, 256>>>();              // fused, in place
    av_kernel<<<dim3(8, NBATCH * NH), 256>>>();               // 1024/128 x 24
    proj_kernel<<<dim3(6, 16), 256>>>(w_out, b_out, out);     // 768/128 x 2048/128
}